// round 2
// baseline (speedup 1.0000x reference)
#include <cuda_runtime.h>
#include <cuda_bf16.h>
#include <math.h>

// ---------------- problem constants ----------------
#define Bsz 64
#define Lseq 256
#define Eemb 128
#define EL 32768           // Eemb * Lseq
#define Hhid 2048
#define Cch 256
#define NCcls 10
#define Lp 128             // Lseq/2
#define DIN 512            // d_inner
#define DST 16             // d_state
#define DTR 16             // dt_rank
#define Mrow 8192          // Bsz*Lp

// ---------------- scratch (static device globals; no allocs) ----------------
__device__ float g_e    [Bsz * EL];          // (B, E*L)
__device__ float g_h1   [Bsz * Hhid];        // (B, H)
__device__ float g_h2   [Bsz * EL];          // (B, L*E)
__device__ float g_ht   [Bsz * EL];          // (B, E, L)
__device__ float g_xs   [Bsz * Lp * Cch];    // (B, Lp, C)
__device__ float g_xz   [Bsz * Lp * 2*DIN];  // (B, Lp, 1024) u|z
__device__ float g_u    [Bsz * Lp * DIN];    // post dwconv+silu
__device__ float g_xdbl [Bsz * Lp * 48];     // dt|Bm|Cm
__device__ float g_delta[Bsz * Lp * DIN];
__device__ float g_y    [Bsz * Lp * DIN];
__device__ float g_ymean[Bsz * Cch];

// ---------------- small elementwise kernels ----------------
__global__ void embed_gather(const int* __restrict__ x, const float4* __restrict__ emb,
                             float4* __restrict__ e4) {
    int f = blockIdx.x * 256 + threadIdx.x;           // 524288 float4s
    if (f >= Bsz * Lseq * (Eemb/4)) return;
    int w = f >> 5;                                    // b*L + l  (E=128 -> 32 float4/row)
    int q = f & 31;
    int tok = x[w];
    e4[f] = emb[tok * 32 + q];
}

__global__ void init_bias(float* __restrict__ out, const float* __restrict__ b,
                          int total, int N) {
    int i = blockIdx.x * 256 + threadIdx.x;
    if (i < total) out[i] = b[i % N];
}

__global__ void relu_inplace(float* __restrict__ p, int n) {
    int i = blockIdx.x * 256 + threadIdx.x;
    if (i < n) p[i] = fmaxf(p[i], 0.f);
}

__global__ void zero_buf(float* __restrict__ p, int n) {
    int i = blockIdx.x * 256 + threadIdx.x;
    if (i < n) p[i] = 0.f;
}

// ---------------- generic NT GEMM: out[m][n] = sum_k A[m*lda+k] * W[n*ldw+k] ----------------
// MODE: 0 = direct write (bias/act fused), 1 = atomicAdd raw partials,
//       2 = mean-pool over 128 rows: atomicAdd(out[(m>>7)*N+n], acc/128)
// ACT : 0 none, 1 relu, 2 softplus
template<int MODE, int ACT, bool HAS_BIAS>
__global__ void gemm_nt(const float* __restrict__ A, int lda,
                        const float* __restrict__ W, int ldw,
                        float* __restrict__ out, const float* __restrict__ bias,
                        int M, int N, int K, int kChunk)
{
    __shared__ float As[16][72];
    __shared__ float Ws[16][72];
    const int m0 = blockIdx.x * 64;
    const int n0 = blockIdx.y * 64;
    const int kBeg = blockIdx.z * kChunk;
    const int kEnd = min(K, kBeg + kChunk);
    const int tid = threadIdx.x;
    const int tm = tid & 15, tn = tid >> 4;
    const int lr = tid >> 2;            // 0..63 tile row
    const int lk = (tid & 3) * 4;       // 0,4,8,12

    float acc[4][4];
#pragma unroll
    for (int i = 0; i < 4; i++)
#pragma unroll
        for (int j = 0; j < 4; j++) acc[i][j] = 0.f;

    for (int k0 = kBeg; k0 < kEnd; k0 += 16) {
#pragma unroll
        for (int j = 0; j < 4; j++) {
            int k = k0 + lk + j;
            int m = m0 + lr;
            As[lk + j][lr] = (m < M && k < K) ? A[m * lda + k] : 0.f;
            int n = n0 + lr;
            Ws[lk + j][lr] = (n < N && k < K) ? W[n * ldw + k] : 0.f;
        }
        __syncthreads();
#pragma unroll
        for (int k = 0; k < 16; k++) {
            float4 av = *(const float4*)(&As[k][tm * 4]);
            float4 bv = *(const float4*)(&Ws[k][tn * 4]);
            float a[4] = {av.x, av.y, av.z, av.w};
            float b[4] = {bv.x, bv.y, bv.z, bv.w};
#pragma unroll
            for (int i = 0; i < 4; i++)
#pragma unroll
                for (int j = 0; j < 4; j++) acc[i][j] += a[i] * b[j];
        }
        __syncthreads();
    }

#pragma unroll
    for (int i = 0; i < 4; i++) {
        int m = m0 + tm * 4 + i;
        if (m >= M) continue;
#pragma unroll
        for (int j = 0; j < 4; j++) {
            int n = n0 + tn * 4 + j;
            if (n >= N) continue;
            float v = acc[i][j];
            if (MODE == 0) {
                if (HAS_BIAS) v += bias[n];
                if (ACT == 1) v = fmaxf(v, 0.f);
                if (ACT == 2) v = (v > 20.f) ? v : log1pf(expf(v));
                out[m * N + n] = v;
            } else if (MODE == 1) {
                atomicAdd(&out[m * N + n], v);
            } else {
                atomicAdd(&out[(m >> 7) * N + n], v * (1.f / 128.f));
            }
        }
    }
}

// ---------------- transpose h2: (B, L, E) -> (B, E, L) ----------------
__global__ void transpose_h2(const float* __restrict__ h2, float* __restrict__ ht) {
    __shared__ float t[32][33];
    int b = blockIdx.x, l0 = blockIdx.y * 32, e0 = blockIdx.z * 32;
    int tx = threadIdx.x, ty = threadIdx.y;       // (32, 8)
#pragma unroll
    for (int r = 0; r < 4; r++)
        t[ty + r * 8][tx] = h2[b * EL + (l0 + ty + r * 8) * Eemb + e0 + tx];
    __syncthreads();
#pragma unroll
    for (int r = 0; r < 4; r++)
        ht[b * EL + (e0 + ty + r * 8) * Lseq + l0 + tx] = t[tx][ty + r * 8];
}

// ---------------- conv1d(k=5,pad=2) + bias + relu + maxpool2 -> xs (B,Lp,C) ----------------
__global__ void conv_pool(const float* __restrict__ ht, const float* __restrict__ cw,
                          const float* __restrict__ cb, float* __restrict__ xs) {
    __shared__ float in_s[16][260];
    __shared__ float w_s[32][81];
    int b = blockIdx.x, c0 = blockIdx.y * 32;
    int tid = threadIdx.x;
    int tq = tid & 31, cgrp = tid >> 5;          // lane = l-slot, group = 4-c set

    float acc[4][8];
#pragma unroll
    for (int i = 0; i < 4; i++)
#pragma unroll
        for (int j = 0; j < 8; j++) acc[i][j] = 0.f;

    for (int e0 = 0; e0 < Eemb; e0 += 16) {
        for (int i = tid; i < 16 * 260; i += 256) {
            int ec = i / 260, p = i % 260, l = p - 2;
            in_s[ec][p] = (l >= 0 && l < Lseq) ? ht[b * EL + (e0 + ec) * Lseq + l] : 0.f;
        }
        for (int i = tid; i < 32 * 80; i += 256) {
            int cl = i / 80, q = i % 80;
            w_s[cl][q] = cw[(c0 + cl) * (Eemb * 5) + e0 * 5 + q];
        }
        __syncthreads();
        for (int ec = 0; ec < 16; ec++) {
            float w5[4][5];
#pragma unroll
            for (int i = 0; i < 4; i++)
#pragma unroll
                for (int t = 0; t < 5; t++) w5[i][t] = w_s[cgrp * 4 + i][ec * 5 + t];
#pragma unroll
            for (int j = 0; j < 8; j++) {
                float xv[5];
#pragma unroll
                for (int t = 0; t < 5; t++) xv[t] = in_s[ec][tq + 32 * j + t];
#pragma unroll
                for (int i = 0; i < 4; i++)
#pragma unroll
                    for (int t = 0; t < 5; t++) acc[i][j] += xv[t] * w5[i][t];
            }
        }
        __syncthreads();
    }

    const unsigned mask = 0xffffffffu;
#pragma unroll
    for (int i = 0; i < 4; i++) {
        int c = c0 + cgrp * 4 + i;
        float cbv = cb[c];
#pragma unroll
        for (int j = 0; j < 8; j++) {
            float v = acc[i][j] + cbv;
            float o = __shfl_down_sync(mask, v, 1);   // partner holds l+1
            if ((tq & 1) == 0) {
                int lp = (tq + 32 * j) >> 1;
                xs[(b * Lp + lp) * Cch + c] = fmaxf(fmaxf(v, o), 0.f);
            }
        }
    }
}

// ---------------- depthwise causal conv1d (k=4) + bias + SiLU on u ----------------
__global__ void dwconv_silu(const float* __restrict__ xz, const float* __restrict__ c1w,
                            const float* __restrict__ c1b, float* __restrict__ u) {
    int idx = blockIdx.x * 256 + threadIdx.x;
    if (idx >= Mrow * DIN) return;
    int d = idx & (DIN - 1);
    int m = idx >> 9;                // b*Lp + lp
    int lp = m & (Lp - 1), b = m >> 7;
    float acc = c1b[d];
#pragma unroll
    for (int t = 0; t < 4; t++) {
        int lq = lp - 3 + t;
        if (lq >= 0) acc += xz[(b * Lp + lq) * (2 * DIN) + d] * c1w[d * 4 + t];
    }
    u[idx] = acc / (1.f + __expf(-acc));
}

// ---------------- selective scan: one thread per (b, d) ----------------
__global__ void scan_kernel(const float* __restrict__ delta_g, const float* __restrict__ u_g,
                            const float* __restrict__ xdbl, const float* __restrict__ xz,
                            const float* __restrict__ A_log, const float* __restrict__ Dp,
                            float* __restrict__ y_g) {
    int gid = blockIdx.x * 256 + threadIdx.x;
    if (gid >= Bsz * DIN) return;
    int d = gid & (DIN - 1), b = gid >> 9;

    float An[DST], h[DST];
#pragma unroll
    for (int n = 0; n < DST; n++) { An[n] = -__expf(A_log[d * DST + n]); h[n] = 0.f; }
    float Dv = Dp[d];

    for (int lp = 0; lp < Lp; lp++) {
        int m = b * Lp + lp;
        float delta = delta_g[m * DIN + d];
        float uu = u_g[m * DIN + d];
        float du = delta * uu;
        const float4* Bp = (const float4*)(xdbl + m * 48 + 16);
        const float4* Cp = (const float4*)(xdbl + m * 48 + 32);
        float Bv[DST], Cv[DST];
#pragma unroll
        for (int q = 0; q < 4; q++) {
            float4 t = Bp[q];
            Bv[4*q] = t.x; Bv[4*q+1] = t.y; Bv[4*q+2] = t.z; Bv[4*q+3] = t.w;
            float4 t2 = Cp[q];
            Cv[4*q] = t2.x; Cv[4*q+1] = t2.y; Cv[4*q+2] = t2.z; Cv[4*q+3] = t2.w;
        }
        float acc = 0.f;
#pragma unroll
        for (int n = 0; n < DST; n++) {
            h[n] = __expf(delta * An[n]) * h[n] + du * Bv[n];
            acc += h[n] * Cv[n];
        }
        float z = xz[m * (2 * DIN) + DIN + d];
        y_g[m * DIN + d] = (acc + uu * Dv) * (z / (1.f + __expf(-z)));
    }
}

// ---------------- final FC: one warp per (b, nc) ----------------
__global__ void fc_kernel(const float* __restrict__ ymean, const float* __restrict__ fcw,
                          const float* __restrict__ fcb, float* __restrict__ out) {
    int o = blockIdx.x;                  // 640
    int b = o / NCcls, nc = o % NCcls;
    int lane = threadIdx.x;
    float acc = 0.f;
    for (int c = lane; c < Cch; c += 32)
        acc += ymean[b * Cch + c] * fcw[nc * Cch + c];
#pragma unroll
    for (int s = 16; s; s >>= 1) acc += __shfl_xor_sync(0xffffffffu, acc, s);
    if (lane == 0) out[o] = acc + fcb[nc];
}

// ---------------- launcher ----------------
extern "C" void kernel_launch(void* const* d_in, const int* in_sizes, int n_in,
                              void* d_out, int out_size) {
    const int*   x         = (const int*)  d_in[0];
    const float* embed     = (const float*)d_in[1];
    const float* enc_w1    = (const float*)d_in[2];
    const float* enc_b1    = (const float*)d_in[3];
    const float* enc_w2    = (const float*)d_in[4];
    const float* enc_b2    = (const float*)d_in[5];
    const float* conv_w    = (const float*)d_in[6];
    const float* conv_b    = (const float*)d_in[7];
    const float* in_proj_w = (const float*)d_in[8];
    const float* conv1d_w  = (const float*)d_in[9];
    const float* conv1d_b  = (const float*)d_in[10];
    const float* x_proj_w  = (const float*)d_in[11];
    const float* dt_proj_w = (const float*)d_in[12];
    const float* dt_proj_b = (const float*)d_in[13];
    const float* A_log     = (const float*)d_in[14];
    const float* Dp        = (const float*)d_in[15];
    const float* out_proj_w= (const float*)d_in[16];
    const float* fc_w      = (const float*)d_in[17];
    const float* fc_b      = (const float*)d_in[18];
    float* out = (float*)d_out;

    float *e, *h1, *h2, *ht, *xs, *xz, *u, *xdbl, *delta, *y, *ymean;
    cudaGetSymbolAddress((void**)&e,     g_e);
    cudaGetSymbolAddress((void**)&h1,    g_h1);
    cudaGetSymbolAddress((void**)&h2,    g_h2);
    cudaGetSymbolAddress((void**)&ht,    g_ht);
    cudaGetSymbolAddress((void**)&xs,    g_xs);
    cudaGetSymbolAddress((void**)&xz,    g_xz);
    cudaGetSymbolAddress((void**)&u,     g_u);
    cudaGetSymbolAddress((void**)&xdbl,  g_xdbl);
    cudaGetSymbolAddress((void**)&delta, g_delta);
    cudaGetSymbolAddress((void**)&y,     g_y);
    cudaGetSymbolAddress((void**)&ymean, g_ymean);

    // 1) embedding gather -> e (B, E*L)
    embed_gather<<<2048, 256>>>(x, (const float4*)embed, (float4*)e);

    // 2) h1 = relu(e @ W1^T + b1): init bias, k-split atomic GEMM, relu
    init_bias<<<(Bsz*Hhid + 255)/256, 256>>>(h1, enc_b1, Bsz*Hhid, Hhid);
    gemm_nt<1, 0, false><<<dim3(1, 32, 16), 256>>>(e, EL, enc_w1, EL, h1, nullptr,
                                                   Bsz, Hhid, EL, EL/16);
    relu_inplace<<<(Bsz*Hhid + 255)/256, 256>>>(h1, Bsz*Hhid);

    // 3) h2 = relu(h1 @ W2^T + b2)
    gemm_nt<0, 1, true><<<dim3(1, 512, 1), 256>>>(h1, Hhid, enc_w2, Hhid, h2, enc_b2,
                                                  Bsz, EL, Hhid, Hhid);

    // 4) transpose to (B, E, L) then conv+relu+pool -> xs (B, Lp, C)
    transpose_h2<<<dim3(Bsz, Lseq/32, Eemb/32), dim3(32, 8)>>>(h2, ht);
    conv_pool<<<dim3(Bsz, Cch/32), 256>>>(ht, conv_w, conv_b, xs);

    // 5) in_proj: xz = xs @ in_proj_w^T   (8192 x 1024 x 256)
    gemm_nt<0, 0, false><<<dim3(Mrow/64, 16, 1), 256>>>(xs, Cch, in_proj_w, Cch, xz, nullptr,
                                                        Mrow, 2*DIN, Cch, Cch);

    // 6) depthwise causal conv + SiLU -> u
    dwconv_silu<<<(Mrow*DIN + 255)/256, 256>>>(xz, conv1d_w, conv1d_b, u);

    // 7) x_proj: xdbl = u @ x_proj_w^T   (8192 x 48 x 512)
    gemm_nt<0, 0, false><<<dim3(Mrow/64, 1, 1), 256>>>(u, DIN, x_proj_w, DIN, xdbl, nullptr,
                                                       Mrow, 48, DIN, DIN);

    // 8) delta = softplus(dt @ dt_proj_w^T + b)   (8192 x 512 x 16), A lda=48
    gemm_nt<0, 2, true><<<dim3(Mrow/64, 8, 1), 256>>>(xdbl, 48, dt_proj_w, DTR, delta, dt_proj_b,
                                                      Mrow, DIN, DTR, DTR);

    // 9) selective scan (+ u*D + silu(z) gate) -> y
    scan_kernel<<<(Bsz*DIN)/256, 256>>>(delta, u, xdbl, xz, A_log, Dp, y);

    // 10) out_proj with fused mean-pool over Lp -> ymean (B, C)
    zero_buf<<<(Bsz*Cch + 255)/256, 256>>>(ymean, Bsz*Cch);
    gemm_nt<2, 0, false><<<dim3(Mrow/64, 4, 1), 256>>>(y, DIN, out_proj_w, DIN, ymean, nullptr,
                                                       Mrow, Cch, DIN, DIN);

    // 11) final FC -> (B, NC)
    fc_kernel<<<Bsz*NCcls, 32>>>(ymean, fc_w, fc_b, out);
}

// round 3
// speedup vs baseline: 1.8143x; 1.8143x over previous
#include <cuda_runtime.h>
#include <cuda_bf16.h>
#include <math.h>

// ---------------- problem constants ----------------
#define Bsz 64
#define Lseq 256
#define Eemb 128
#define EL 32768           // Eemb * Lseq
#define Hhid 2048
#define Cch 256
#define NCcls 10
#define Lp 128             // Lseq/2
#define DIN 512            // d_inner
#define DST 16             // d_state
#define DTR 16             // dt_rank
#define Mrow 8192          // Bsz*Lp

// ---------------- scratch (static device globals; no allocs) ----------------
__device__ float g_e    [Bsz * EL];          // (B, E*L)
__device__ float g_h1   [Bsz * Hhid];        // (B, H)
__device__ float g_h2   [Bsz * EL];          // (B, L*E)
__device__ float g_ht   [Bsz * EL];          // (B, E, L)
__device__ float g_xs   [Bsz * Lp * Cch];    // (B, Lp, C)
__device__ float g_xz   [Bsz * Lp * 2*DIN];  // (B, Lp, 1024) u|z
__device__ float g_u    [Bsz * Lp * DIN];    // post dwconv+silu
__device__ float g_xdbl [Bsz * Lp * 48];     // dt|Bm|Cm
__device__ float g_delta[Bsz * Lp * DIN];
__device__ float g_y    [Bsz * Lp * DIN];
__device__ float g_ymean[Bsz * Cch];

// ---------------- small elementwise kernels ----------------
__global__ void embed_gather(const int* __restrict__ x, const float4* __restrict__ emb,
                             float4* __restrict__ e4) {
    int f = blockIdx.x * 256 + threadIdx.x;           // 524288 float4s
    if (f >= Bsz * Lseq * (Eemb/4)) return;
    int w = f >> 5;                                    // b*L + l  (E=128 -> 32 float4/row)
    int q = f & 31;
    int tok = x[w];
    e4[f] = emb[tok * 32 + q];
}

__global__ void init_bias(float* __restrict__ out, const float* __restrict__ b,
                          int total, int N) {
    int i = blockIdx.x * 256 + threadIdx.x;
    if (i < total) out[i] = b[i % N];
}

__global__ void relu_inplace(float* __restrict__ p, int n) {
    int i = blockIdx.x * 256 + threadIdx.x;
    if (i < n) p[i] = fmaxf(p[i], 0.f);
}

__global__ void zero_buf(float* __restrict__ p, int n) {
    int i = blockIdx.x * 256 + threadIdx.x;
    if (i < n) p[i] = 0.f;
}

// ---------------- bf16 split helpers ----------------
__device__ __forceinline__ void cvt_split(float x, float y, unsigned& hi, unsigned& lo) {
    __nv_bfloat16 hx = __float2bfloat16(x);
    __nv_bfloat16 hy = __float2bfloat16(y);
    float rx = x - __bfloat162float(hx);
    float ry = y - __bfloat162float(hy);
    __nv_bfloat162 hp = __halves2bfloat162(hx, hy);
    __nv_bfloat162 lp = __floats2bfloat162_rn(rx, ry);
    hi = *reinterpret_cast<unsigned*>(&hp);
    lo = *reinterpret_cast<unsigned*>(&lp);
}

__device__ __forceinline__ void mma16816(float* c, const uint4& a, const uint2& b) {
    asm volatile(
        "mma.sync.aligned.m16n8k16.row.col.f32.bf16.bf16.f32 "
        "{%0,%1,%2,%3}, {%4,%5,%6,%7}, {%8,%9}, {%0,%1,%2,%3};"
        : "+f"(c[0]), "+f"(c[1]), "+f"(c[2]), "+f"(c[3])
        : "r"(a.x), "r"(a.y), "r"(a.z), "r"(a.w), "r"(b.x), "r"(b.y));
}

// ---------------- tensor-core NT GEMM with fused fp32->bf16(hi,lo) split ------------
// out[m][n] = sum_k A[m*lda+k] * W[n*ldw+k]
// Requires: all of (M block-range, N, K, kChunk) multiples of 64; no bounds checks.
// Block tile: 64x64, BK=64, 256 threads (8 warps: 4 in m, 2 in n each covering 32 cols).
// MODE: 0 direct write (+bias/act), 1 atomicAdd, 2 mean-pool over 128 rows (atomic).
// ACT : 0 none, 1 relu.
template<int MODE, int ACT, bool HAS_BIAS>
__global__ void gemm_mma(const float* __restrict__ A, int lda,
                         const float* __restrict__ W, int ldw,
                         float* __restrict__ out, const float* __restrict__ bias,
                         int N, int kChunk)
{
    // fragments stored in canonical mma layout: [prec][kt][tile][lane*regs]
    __shared__ unsigned As_s[2][4][4][128];   // A: 4 ktiles x 4 mtiles, 4 regs/lane
    __shared__ unsigned Bs_s[2][4][8][64];    // B: 4 ktiles x 8 ntiles, 2 regs/lane

    const int tid  = threadIdx.x;
    const int lane = tid & 31;
    const int w    = tid >> 5;
    const int mt   = w & 3;            // m-tile of this warp (16 rows)
    const int ntg  = (w >> 2) * 4;     // first n-tile (4 tiles of 8 = 32 cols)

    const int m0   = blockIdx.x * 64;
    const int n0   = blockIdx.y * 64;
    const int kBeg = blockIdx.z * kChunk;
    const int kEnd = kBeg + kChunk;

    float acc[4][4];
#pragma unroll
    for (int i = 0; i < 4; i++)
#pragma unroll
        for (int j = 0; j < 4; j++) acc[i][j] = 0.f;

    for (int k0 = kBeg; k0 < kEnd; k0 += 64) {
        // ---- load + convert A tile (64 m x 64 k) ----
#pragma unroll
        for (int i = 0; i < 8; i++) {
            int idx = tid + i * 256;           // 2048 float2-pairs
            int m  = idx >> 5;
            int k  = (idx & 31) * 2;
            float2 v = *reinterpret_cast<const float2*>(&A[(m0 + m) * (long)lda + k0 + k]);
            unsigned hp, lp;
            cvt_split(v.x, v.y, hp, lp);
            int kt = k >> 4, kk = k & 15;
            int r  = m & 15;
            int ln = (r & 7) * 4 + ((kk & 7) >> 1);
            int rg = ((kk >> 3) << 1) | (r >> 3);
            As_s[0][kt][m >> 4][ln * 4 + rg] = hp;
            As_s[1][kt][m >> 4][ln * 4 + rg] = lp;
        }
        // ---- load + convert W tile (64 n x 64 k) ----
#pragma unroll
        for (int i = 0; i < 8; i++) {
            int idx = tid + i * 256;
            int n  = idx >> 5;
            int k  = (idx & 31) * 2;
            float2 v = *reinterpret_cast<const float2*>(&W[(n0 + n) * (long)ldw + k0 + k]);
            unsigned hp, lp;
            cvt_split(v.x, v.y, hp, lp);
            int kt = k >> 4, kk = k & 15;
            int nn = n & 7;
            int ln = nn * 4 + ((kk & 7) >> 1);
            int rg = kk >> 3;
            Bs_s[0][kt][n >> 3][ln * 2 + rg] = hp;
            Bs_s[1][kt][n >> 3][ln * 2 + rg] = lp;
        }
        __syncthreads();

        // ---- compute ----
#pragma unroll
        for (int kt = 0; kt < 4; kt++) {
            uint4 ah = *reinterpret_cast<const uint4*>(&As_s[0][kt][mt][lane * 4]);
            uint4 al = *reinterpret_cast<const uint4*>(&As_s[1][kt][mt][lane * 4]);
#pragma unroll
            for (int nt = 0; nt < 4; nt++) {
                uint2 bh = *reinterpret_cast<const uint2*>(&Bs_s[0][kt][ntg + nt][lane * 2]);
                uint2 bl = *reinterpret_cast<const uint2*>(&Bs_s[1][kt][ntg + nt][lane * 2]);
                mma16816(acc[nt], ah, bh);
                mma16816(acc[nt], ah, bl);
                mma16816(acc[nt], al, bh);
            }
        }
        __syncthreads();
    }

    // ---- epilogue ----
    const int g   = lane >> 2;
    const int tig = lane & 3;
    const int rA  = m0 + mt * 16 + g;       // rows rA and rA+8
#pragma unroll
    for (int nt = 0; nt < 4; nt++) {
        int c = n0 + (ntg + nt) * 8 + tig * 2;
#pragma unroll
        for (int h = 0; h < 2; h++) {       // h=0 -> row rA, h=1 -> row rA+8
            int m = rA + h * 8;
#pragma unroll
            for (int q = 0; q < 2; q++) {   // column c+q
                float v = acc[nt][h * 2 + q];
                int n = c + q;
                if (MODE == 0) {
                    if (HAS_BIAS) v += bias[n];
                    if (ACT == 1) v = fmaxf(v, 0.f);
                    out[m * N + n] = v;
                } else if (MODE == 1) {
                    atomicAdd(&out[m * N + n], v);
                } else {
                    atomicAdd(&out[(m >> 7) * N + n], v * (1.f / 128.f));
                }
            }
        }
    }
}

// ---------------- generic fp32 NT GEMM (kept for small/odd shapes) ----------------
// MODE: 0 = direct write (bias/act fused). ACT : 0 none, 1 relu, 2 softplus
template<int MODE, int ACT, bool HAS_BIAS>
__global__ void gemm_nt(const float* __restrict__ A, int lda,
                        const float* __restrict__ W, int ldw,
                        float* __restrict__ out, const float* __restrict__ bias,
                        int M, int N, int K, int kChunk)
{
    __shared__ float As[16][72];
    __shared__ float Ws[16][72];
    const int m0 = blockIdx.x * 64;
    const int n0 = blockIdx.y * 64;
    const int kBeg = blockIdx.z * kChunk;
    const int kEnd = min(K, kBeg + kChunk);
    const int tid = threadIdx.x;
    const int tm = tid & 15, tn = tid >> 4;
    const int lr = tid >> 2;            // 0..63 tile row
    const int lk = (tid & 3) * 4;       // 0,4,8,12

    float acc[4][4];
#pragma unroll
    for (int i = 0; i < 4; i++)
#pragma unroll
        for (int j = 0; j < 4; j++) acc[i][j] = 0.f;

    for (int k0 = kBeg; k0 < kEnd; k0 += 16) {
#pragma unroll
        for (int j = 0; j < 4; j++) {
            int k = k0 + lk + j;
            int m = m0 + lr;
            As[lk + j][lr] = (m < M && k < K) ? A[m * lda + k] : 0.f;
            int n = n0 + lr;
            Ws[lk + j][lr] = (n < N && k < K) ? W[n * ldw + k] : 0.f;
        }
        __syncthreads();
#pragma unroll
        for (int k = 0; k < 16; k++) {
            float4 av = *(const float4*)(&As[k][tm * 4]);
            float4 bv = *(const float4*)(&Ws[k][tn * 4]);
            float a[4] = {av.x, av.y, av.z, av.w};
            float b[4] = {bv.x, bv.y, bv.z, bv.w};
#pragma unroll
            for (int i = 0; i < 4; i++)
#pragma unroll
                for (int j = 0; j < 4; j++) acc[i][j] += a[i] * b[j];
        }
        __syncthreads();
    }

#pragma unroll
    for (int i = 0; i < 4; i++) {
        int m = m0 + tm * 4 + i;
        if (m >= M) continue;
#pragma unroll
        for (int j = 0; j < 4; j++) {
            int n = n0 + tn * 4 + j;
            if (n >= N) continue;
            float v = acc[i][j];
            if (MODE == 0) {
                if (HAS_BIAS) v += bias[n];
                if (ACT == 1) v = fmaxf(v, 0.f);
                if (ACT == 2) v = (v > 20.f) ? v : log1pf(expf(v));
                out[m * N + n] = v;
            } else if (MODE == 1) {
                atomicAdd(&out[m * N + n], v);
            } else {
                atomicAdd(&out[(m >> 7) * N + n], v * (1.f / 128.f));
            }
        }
    }
}

// ---------------- transpose h2: (B, L, E) -> (B, E, L) ----------------
__global__ void transpose_h2(const float* __restrict__ h2, float* __restrict__ ht) {
    __shared__ float t[32][33];
    int b = blockIdx.x, l0 = blockIdx.y * 32, e0 = blockIdx.z * 32;
    int tx = threadIdx.x, ty = threadIdx.y;       // (32, 8)
#pragma unroll
    for (int r = 0; r < 4; r++)
        t[ty + r * 8][tx] = h2[b * EL + (l0 + ty + r * 8) * Eemb + e0 + tx];
    __syncthreads();
#pragma unroll
    for (int r = 0; r < 4; r++)
        ht[b * EL + (e0 + ty + r * 8) * Lseq + l0 + tx] = t[tx][ty + r * 8];
}

// ---------------- conv1d(k=5,pad=2) + bias + relu + maxpool2 -> xs (B,Lp,C) ----------------
__global__ void conv_pool(const float* __restrict__ ht, const float* __restrict__ cw,
                          const float* __restrict__ cb, float* __restrict__ xs) {
    __shared__ float in_s[16][260];
    __shared__ float w_s[32][81];
    int b = blockIdx.x, c0 = blockIdx.y * 32;
    int tid = threadIdx.x;
    int tq = tid & 31, cgrp = tid >> 5;          // lane = l-slot, group = 4-c set

    float acc[4][8];
#pragma unroll
    for (int i = 0; i < 4; i++)
#pragma unroll
        for (int j = 0; j < 8; j++) acc[i][j] = 0.f;

    for (int e0 = 0; e0 < Eemb; e0 += 16) {
        for (int i = tid; i < 16 * 260; i += 256) {
            int ec = i / 260, p = i % 260, l = p - 2;
            in_s[ec][p] = (l >= 0 && l < Lseq) ? ht[b * EL + (e0 + ec) * Lseq + l] : 0.f;
        }
        for (int i = tid; i < 32 * 80; i += 256) {
            int cl = i / 80, q = i % 80;
            w_s[cl][q] = cw[(c0 + cl) * (Eemb * 5) + e0 * 5 + q];
        }
        __syncthreads();
        for (int ec = 0; ec < 16; ec++) {
            float w5[4][5];
#pragma unroll
            for (int i = 0; i < 4; i++)
#pragma unroll
                for (int t = 0; t < 5; t++) w5[i][t] = w_s[cgrp * 4 + i][ec * 5 + t];
#pragma unroll
            for (int j = 0; j < 8; j++) {
                float xv[5];
#pragma unroll
                for (int t = 0; t < 5; t++) xv[t] = in_s[ec][tq + 32 * j + t];
#pragma unroll
                for (int i = 0; i < 4; i++)
#pragma unroll
                    for (int t = 0; t < 5; t++) acc[i][j] += xv[t] * w5[i][t];
            }
        }
        __syncthreads();
    }

    const unsigned mask = 0xffffffffu;
#pragma unroll
    for (int i = 0; i < 4; i++) {
        int c = c0 + cgrp * 4 + i;
        float cbv = cb[c];
#pragma unroll
        for (int j = 0; j < 8; j++) {
            float v = acc[i][j] + cbv;
            float o = __shfl_down_sync(mask, v, 1);   // partner holds l+1
            if ((tq & 1) == 0) {
                int lp = (tq + 32 * j) >> 1;
                xs[(b * Lp + lp) * Cch + c] = fmaxf(fmaxf(v, o), 0.f);
            }
        }
    }
}

// ---------------- depthwise causal conv1d (k=4) + bias + SiLU on u ----------------
__global__ void dwconv_silu(const float* __restrict__ xz, const float* __restrict__ c1w,
                            const float* __restrict__ c1b, float* __restrict__ u) {
    int idx = blockIdx.x * 256 + threadIdx.x;
    if (idx >= Mrow * DIN) return;
    int d = idx & (DIN - 1);
    int m = idx >> 9;                // b*Lp + lp
    int lp = m & (Lp - 1), b = m >> 7;
    float acc = c1b[d];
#pragma unroll
    for (int t = 0; t < 4; t++) {
        int lq = lp - 3 + t;
        if (lq >= 0) acc += xz[(b * Lp + lq) * (2 * DIN) + d] * c1w[d * 4 + t];
    }
    u[idx] = acc / (1.f + __expf(-acc));
}

// ---------------- selective scan: one thread per (b, d) ----------------
__global__ void scan_kernel(const float* __restrict__ delta_g, const float* __restrict__ u_g,
                            const float* __restrict__ xdbl, const float* __restrict__ xz,
                            const float* __restrict__ A_log, const float* __restrict__ Dp,
                            float* __restrict__ y_g) {
    int gid = blockIdx.x * 256 + threadIdx.x;
    if (gid >= Bsz * DIN) return;
    int d = gid & (DIN - 1), b = gid >> 9;

    float An[DST], h[DST];
#pragma unroll
    for (int n = 0; n < DST; n++) { An[n] = -__expf(A_log[d * DST + n]); h[n] = 0.f; }
    float Dv = Dp[d];

    for (int lp = 0; lp < Lp; lp++) {
        int m = b * Lp + lp;
        float delta = delta_g[m * DIN + d];
        float uu = u_g[m * DIN + d];
        float du = delta * uu;
        const float4* Bp = (const float4*)(xdbl + m * 48 + 16);
        const float4* Cp = (const float4*)(xdbl + m * 48 + 32);
        float Bv[DST], Cv[DST];
#pragma unroll
        for (int q = 0; q < 4; q++) {
            float4 t = Bp[q];
            Bv[4*q] = t.x; Bv[4*q+1] = t.y; Bv[4*q+2] = t.z; Bv[4*q+3] = t.w;
            float4 t2 = Cp[q];
            Cv[4*q] = t2.x; Cv[4*q+1] = t2.y; Cv[4*q+2] = t2.z; Cv[4*q+3] = t2.w;
        }
        float acc = 0.f;
#pragma unroll
        for (int n = 0; n < DST; n++) {
            h[n] = __expf(delta * An[n]) * h[n] + du * Bv[n];
            acc += h[n] * Cv[n];
        }
        float z = xz[m * (2 * DIN) + DIN + d];
        y_g[m * DIN + d] = (acc + uu * Dv) * (z / (1.f + __expf(-z)));
    }
}

// ---------------- final FC: one warp per (b, nc) ----------------
__global__ void fc_kernel(const float* __restrict__ ymean, const float* __restrict__ fcw,
                          const float* __restrict__ fcb, float* __restrict__ out) {
    int o = blockIdx.x;                  // 640
    int b = o / NCcls, nc = o % NCcls;
    int lane = threadIdx.x;
    float acc = 0.f;
    for (int c = lane; c < Cch; c += 32)
        acc += ymean[b * Cch + c] * fcw[nc * Cch + c];
#pragma unroll
    for (int s = 16; s; s >>= 1) acc += __shfl_xor_sync(0xffffffffu, acc, s);
    if (lane == 0) out[o] = acc + fcb[nc];
}

// ---------------- launcher ----------------
extern "C" void kernel_launch(void* const* d_in, const int* in_sizes, int n_in,
                              void* d_out, int out_size) {
    const int*   x         = (const int*)  d_in[0];
    const float* embed     = (const float*)d_in[1];
    const float* enc_w1    = (const float*)d_in[2];
    const float* enc_b1    = (const float*)d_in[3];
    const float* enc_w2    = (const float*)d_in[4];
    const float* enc_b2    = (const float*)d_in[5];
    const float* conv_w    = (const float*)d_in[6];
    const float* conv_b    = (const float*)d_in[7];
    const float* in_proj_w = (const float*)d_in[8];
    const float* conv1d_w  = (const float*)d_in[9];
    const float* conv1d_b  = (const float*)d_in[10];
    const float* x_proj_w  = (const float*)d_in[11];
    const float* dt_proj_w = (const float*)d_in[12];
    const float* dt_proj_b = (const float*)d_in[13];
    const float* A_log     = (const float*)d_in[14];
    const float* Dp        = (const float*)d_in[15];
    const float* out_proj_w= (const float*)d_in[16];
    const float* fc_w      = (const float*)d_in[17];
    const float* fc_b      = (const float*)d_in[18];
    float* out = (float*)d_out;

    float *e, *h1, *h2, *ht, *xs, *xz, *u, *xdbl, *delta, *y, *ymean;
    cudaGetSymbolAddress((void**)&e,     g_e);
    cudaGetSymbolAddress((void**)&h1,    g_h1);
    cudaGetSymbolAddress((void**)&h2,    g_h2);
    cudaGetSymbolAddress((void**)&ht,    g_ht);
    cudaGetSymbolAddress((void**)&xs,    g_xs);
    cudaGetSymbolAddress((void**)&xz,    g_xz);
    cudaGetSymbolAddress((void**)&u,     g_u);
    cudaGetSymbolAddress((void**)&xdbl,  g_xdbl);
    cudaGetSymbolAddress((void**)&delta, g_delta);
    cudaGetSymbolAddress((void**)&y,     g_y);
    cudaGetSymbolAddress((void**)&ymean, g_ymean);

    // 1) embedding gather -> e (B, E*L)
    embed_gather<<<2048, 256>>>(x, (const float4*)embed, (float4*)e);

    // 2) h1 = relu(e @ W1^T + b1): init bias, k-split atomic MMA-GEMM, relu
    init_bias<<<(Bsz*Hhid + 255)/256, 256>>>(h1, enc_b1, Bsz*Hhid, Hhid);
    gemm_mma<1, 0, false><<<dim3(1, 32, 16), 256>>>(e, EL, enc_w1, EL, h1, nullptr,
                                                    Hhid, EL/16);
    relu_inplace<<<(Bsz*Hhid + 255)/256, 256>>>(h1, Bsz*Hhid);

    // 3) h2 = relu(h1 @ W2^T + b2)
    gemm_mma<0, 1, true><<<dim3(1, 512, 1), 256>>>(h1, Hhid, enc_w2, Hhid, h2, enc_b2,
                                                   EL, Hhid);

    // 4) transpose to (B, E, L) then conv+relu+pool -> xs (B, Lp, C)
    transpose_h2<<<dim3(Bsz, Lseq/32, Eemb/32), dim3(32, 8)>>>(h2, ht);
    conv_pool<<<dim3(Bsz, Cch/32), 256>>>(ht, conv_w, conv_b, xs);

    // 5) in_proj: xz = xs @ in_proj_w^T   (8192 x 1024 x 256)
    gemm_mma<0, 0, false><<<dim3(Mrow/64, 16, 1), 256>>>(xs, Cch, in_proj_w, Cch, xz, nullptr,
                                                         2*DIN, Cch);

    // 6) depthwise causal conv + SiLU -> u
    dwconv_silu<<<(Mrow*DIN + 255)/256, 256>>>(xz, conv1d_w, conv1d_b, u);

    // 7) x_proj: xdbl = u @ x_proj_w^T   (8192 x 48 x 512)  (odd N -> fp32 path)
    gemm_nt<0, 0, false><<<dim3(Mrow/64, 1, 1), 256>>>(u, DIN, x_proj_w, DIN, xdbl, nullptr,
                                                       Mrow, 48, DIN, DIN);

    // 8) delta = softplus(dt @ dt_proj_w^T + b)   (8192 x 512 x 16), A lda=48
    gemm_nt<0, 2, true><<<dim3(Mrow/64, 8, 1), 256>>>(xdbl, 48, dt_proj_w, DTR, delta, dt_proj_b,
                                                      Mrow, DIN, DTR, DTR);

    // 9) selective scan (+ u*D + silu(z) gate) -> y
    scan_kernel<<<(Bsz*DIN)/256, 256>>>(delta, u, xdbl, xz, A_log, Dp, y);

    // 10) out_proj with fused mean-pool over Lp -> ymean (B, C)
    zero_buf<<<(Bsz*Cch + 255)/256, 256>>>(ymean, Bsz*Cch);
    gemm_mma<2, 0, false><<<dim3(Mrow/64, 4, 1), 256>>>(y, DIN, out_proj_w, DIN, ymean, nullptr,
                                                        Cch, DIN);

    // 11) final FC -> (B, NC)
    fc_kernel<<<Bsz*NCcls, 32>>>(ymean, fc_w, fc_b, out);
}